// round 5
// baseline (speedup 1.0000x reference)
#include <cuda_runtime.h>
#include <cuda_bf16.h>

// WaveletTransformer_867583394320 — FINAL (machine floor, stability re-bench).
//
// Math: 4-level Haar DWT immediately inverted by its exact IDWT with the same
// detail coefficients. Haar is an orthogonal perfect-reconstruction filter
// bank: one level composes to x * 2c^2 elementwise (c = fp32(1/sqrt(2))),
// so the full pipeline is x * (2c^2)^4 = x * (1 - ~2.4e-7). Measured rel_err
// vs reference: 9.57e-8 (threshold 1e-3). The problem is an identity =>
// optimal kernel is a pure 256 MiB device-to-device copy.
//
// Bandwidth convergence evidence (same data, three engines):
//   R1  SM float4 grid-stride copy            6361 GB/s   bench 84.5us
//   R2  SM + __ldcs/__stcs + 4x MLP batching  6261 GB/s   bench 84.7us
//   R3  copy-engine memcpy node               ~6.4 TB/s   bench 84.0us
//   R4  copy-engine memcpy node (identical)   ~6.4 TB/s   bench 82.4us
// All paths agree at ~6.3-6.4 TB/s = ~80% of 8 TB/s spec: the HBM3e mixed
// read/write turnaround floor (path-independent chip cap, B300_MICROARCH.md).
// Traffic is irreducible (d_out poisoned by harness; data incompressible).
// R3 vs R4 on identical code bounds run-to-run variance at ~1.5us. This round
// re-benches the winner unchanged to confirm stability before final commit.

extern "C" void kernel_launch(void* const* d_in, const int* in_sizes, int n_in,
                              void* d_out, int out_size) {
    const float* x = (const float*)d_in[0];
    float* out = (float*)d_out;
    size_t bytes = (size_t)out_size * sizeof(float);
    // Async D2D on the capture (default) stream: captured as a single memcpy
    // node executed by the copy engine. No allocation, no sync — capture-legal.
    cudaMemcpyAsync(out, x, bytes, cudaMemcpyDeviceToDevice, 0);
}

// round 6
// speedup vs baseline: 1.0057x; 1.0057x over previous
#include <cuda_runtime.h>
#include <cuda_bf16.h>

// WaveletTransformer_867583394320 — FINAL (machine floor).
//
// Math: 4-level Haar DWT immediately inverted by its exact IDWT with the same
// detail coefficients. Haar is an orthogonal perfect-reconstruction filter
// bank: one level composes to x * 2c^2 elementwise (c = fp32(1/sqrt(2))),
// so the full pipeline is x * (2c^2)^4 = x * (1 - ~2.4e-7). Measured rel_err
// vs reference: 9.57e-8 (threshold 1e-3). The problem is an identity =>
// optimal kernel is a pure 256 MiB device-to-device copy.
//
// Measured across rounds (same data, three engines):
//   R1  SM float4 grid-stride copy            6361 GB/s   bench 84.5us
//   R2  SM + __ldcs/__stcs + 4x MLP batching  6261 GB/s   bench 84.7us
//   R3  copy-engine memcpy node               ~6.4 TB/s   bench 84.0us
//   R4  copy-engine memcpy node (identical)   ~6.4 TB/s   bench 82.4us
//   R5  copy-engine memcpy node (identical)   ~6.4 TB/s   bench 84.5us
// All paths converge at ~6.3-6.4 TB/s mixed R+W = ~80% of the 8 TB/s spec:
// the HBM3e read/write-turnaround floor (path-independent per
// B300_MICROARCH.md; LDG.cv ≡ TMA ≡ CE at the chip cap). R3/R4/R5 on
// identical code bound run-to-run variance at ~±1.5us.
//
// Levers audited and closed:
//  - Traffic reduction: impossible (d_out poisoned each run; out == in;
//    data incompressible; 256 MiB read + 256 MiB write irreducible).
//  - Inter-replay L2 persistence (~100MB pinned input -> ~68us): requires
//    the persisting-L2 carveout via cudaDeviceSetLimit, which trips the
//    harness's "device limits changed" guard; without the carveout, any
//    fixed traversal order on a 256MB>126MB footprint is cyclic-LRU thrash
//    with provably zero inter-replay hits.
//  - Concurrent CE+SM split: CE alone already saturates the shared DRAM
//    floor (7.0 TB/s combined R+W); predicted zero gain.
//
// Final: single copy-engine memcpy node — measured-best, one graph node,
// zero kernel-launch overhead, shape-agnostic.

extern "C" void kernel_launch(void* const* d_in, const int* in_sizes, int n_in,
                              void* d_out, int out_size) {
    const float* x = (const float*)d_in[0];
    float* out = (float*)d_out;
    size_t bytes = (size_t)out_size * sizeof(float);
    // Async D2D on the capture (default) stream: captured as a single memcpy
    // node executed by the copy engine. No allocation, no sync — capture-legal.
    cudaMemcpyAsync(out, x, bytes, cudaMemcpyDeviceToDevice, 0);
}

// round 7
// speedup vs baseline: 1.0177x; 1.0119x over previous
#include <cuda_runtime.h>
#include <cuda_bf16.h>

// WaveletTransformer_867583394320 — FINAL (machine floor, converged).
//
// Math: 4-level Haar DWT immediately inverted by its exact IDWT with the same
// detail coefficients. Haar is an orthogonal perfect-reconstruction filter
// bank: one level composes to x * 2c^2 elementwise (c = fp32(1/sqrt(2))),
// so the full pipeline is x * (2c^2)^4 = x * (1 - ~2.4e-7). Measured rel_err
// vs reference: 9.571855e-8 (threshold 1e-3). The problem is an identity =>
// optimal kernel is a pure 256 MiB device-to-device copy.
//
// Measurements (three engines, six rounds):
//   R1  SM float4 grid-stride copy            6361 GB/s   bench 84.5us
//   R2  SM + __ldcs/__stcs + 4x MLP batching  6261 GB/s   bench 84.7us
//   R3-R6  copy-engine memcpy node (identical code):
//          84.0, 82.4, 84.5, 84.0us  -> mean 83.7us, spread ±1.2us
// All paths converge at ~6.4 TB/s combined R+W = ~80% of the 8 TB/s
// bidirectional spec: the HBM3e read/write-turnaround floor, path-independent
// per B300_MICROARCH.md (LDG.cv ≡ TMA ≡ CE at the chip cap). Device time
// 512 MiB / 6.4 TB/s = ~77us; the remaining ~7us is harness graph-replay
// overhead.
//
// Levers audited and closed:
//  - Traffic reduction: impossible (d_out poisoned each replay; out == in;
//    data incompressible; 256 MiB read + 256 MiB write irreducible).
//  - Inter-replay L2 persistence: needs the persisting-L2 carveout via
//    cudaDeviceSetLimit -> trips the harness "device limits changed" guard;
//    without it, a 256MB>126MB cyclic stream gets zero LRU hits.
//  - Concurrent CE+SM split / TMA / write-through policies: same shared
//    DRAM cap, measured or documented path-independent.
//
// Final: single copy-engine memcpy node — one graph node, zero kernel-launch
// overhead, shape-agnostic, at the hardware floor.

extern "C" void kernel_launch(void* const* d_in, const int* in_sizes, int n_in,
                              void* d_out, int out_size) {
    const float* x = (const float*)d_in[0];
    float* out = (float*)d_out;
    size_t bytes = (size_t)out_size * sizeof(float);
    // Async D2D on the capture (default) stream: captured as a single memcpy
    // node executed by the copy engine. No allocation, no sync — capture-legal.
    cudaMemcpyAsync(out, x, bytes, cudaMemcpyDeviceToDevice, 0);
}